// round 6
// baseline (speedup 1.0000x reference)
#include <cuda_runtime.h>
#include <math_constants.h>

#define B_ 32
#define H_ 8
#define L_ 2048
#define E_ 64

#define NTHREADS 128
#define ROWS 32          // rows per block
#define RPC  16          // row-pairs per block
#define SQ 260           // q region stride per rp (256 dup-interleaved words + pad); corr staging aliases
#define SK 132           // k region stride (33 chunks == 1 mod 8 -> LDK broadcast spread)
#define SV 140           // v row stride (128 dup words + pad; 140 mod 32 = 12 spreads gather)

// chunk swizzle: conflict-free for both store pattern (8g+4par+u) and FIR octet pattern (C+4s)
__device__ __forceinline__ int sw(int c) { return c ^ ((c >> 2) & 7); }

// packed f32x2 fma: d = a*b + d (lo = even row, hi = odd row)
__device__ __forceinline__ void ffma2(unsigned long long& d,
                                      unsigned long long a,
                                      unsigned long long b) {
    asm("fma.rn.f32x2 %0, %1, %2, %0;" : "+l"(d) : "l"(a), "l"(b));
}

// AutoCorrelation (Autoformer):
//   corr[b,h,l,d] = sum_e q[b,h,l,(e+d)%64] * k[b,h,l,e]
//   top-4 over d, softmax, V_out[e] = sum_i p_i * v[(e+d_i)%64]
//   outputs: V (B,H,L,E) then corr transposed to (B,E,H,L)
__global__ __launch_bounds__(NTHREADS, 5)
void ac_kernel(const float* __restrict__ Q, const float* __restrict__ Kk,
               const float* __restrict__ Vv, float* __restrict__ outV,
               float* __restrict__ outC)
{
    __shared__ __align__(16) float s_qq[RPC * SQ];   // interleaved (even,odd) q pairs, dup, swizzled
    __shared__ __align__(16) float s_kk[RPC * SK];   // interleaved k pairs, swizzled
    __shared__ __align__(16) float s_v [ROWS * SV];  // v duplicated, plain

    const int t     = threadIdx.x;
    const int lane  = t & 31;
    const int w     = t >> 5;
    const int ltile = blockIdx.x;
    const int bh    = blockIdx.y;
    const int h     = bh & (H_ - 1);
    const int b     = bh >> 3;
    const int l0    = ltile * ROWS;

    // ---------------- load phase: warp owns rows 8w..8w+7 --------------------
    {
        const int g   = lane & 3;          // 4 col-groups of 16 floats
        const int rr  = lane >> 2;         // 8 local rows per warp
        const int par = rr & 1;
        const int rl  = 8 * w + rr;
        const int rpg = rl >> 1;
        const size_t rowbase = ((size_t)bh * L_ + l0 + rl) * (size_t)E_;
        const int col = 16 * g;

        float qa[16], ka[16], va[16];
        #pragma unroll
        for (int u = 0; u < 4; ++u) {
            *(float4*)(qa + 4*u) = *(const float4*)(Q  + rowbase + col + 4*u);
            *(float4*)(ka + 4*u) = *(const float4*)(Kk + rowbase + col + 4*u);
            *(float4*)(va + 4*u) = *(const float4*)(Vv + rowbase + col + 4*u);
        }

        // v: plain + duplicate
        float* vr = s_v + rl * SV;
        #pragma unroll
        for (int u = 0; u < 4; ++u) {
            *(float4*)(vr + col + 4*u)      = *(float4*)(va + 4*u);
            *(float4*)(vr + col + 4*u + 64) = *(float4*)(va + 4*u);
        }

        // parity exchange (lane^4 = other row of same pair, same col-group):
        // par0 sends its high 8 cols, par1 sends its low 8 cols
        float qr[8], kr[8];
        #pragma unroll
        for (int j = 0; j < 8; ++j) {
            float qs = par ? qa[j] : qa[8 + j];
            float ks = par ? ka[j] : ka[8 + j];
            qr[j] = __shfl_xor_sync(0xffffffffu, qs, 4);
            kr[j] = __shfl_xor_sync(0xffffffffu, ks, 4);
        }

        float* qrow = s_qq + rpg * SQ;
        float* krow = s_kk + rpg * SK;
        #pragma unroll
        for (int u = 0; u < 4; ++u) {
            const int c   = 8*g + 4*par + u;       // logical chunk (2 element-pairs)
            const int off = 4 * sw(c);
            float4 fq, fk;
            if (!par) {   // pairs for cols col..col+7: (even=mine, odd=partner)
                fq = make_float4(qa[2*u], qr[2*u], qa[2*u+1], qr[2*u+1]);
                fk = make_float4(ka[2*u], kr[2*u], ka[2*u+1], kr[2*u+1]);
            } else {      // pairs for cols col+8..col+15: (even=partner, odd=mine)
                fq = make_float4(qr[2*u], qa[8+2*u], qr[2*u+1], qa[8+2*u+1]);
                fk = make_float4(kr[2*u], ka[8+2*u], kr[2*u+1], ka[8+2*u+1]);
            }
            *(float4*)(qrow + off)       = fq;
            *(float4*)(qrow + off + 128) = fq;     // duplicate: sw(c+32) == sw(c)+32
            *(float4*)(krow + off)       = fk;
        }
    }
    __syncwarp();

    // ---------------- FIR correlation: 8 delays/lane, f32x2, 2 rows/lane -----
    const int s   = lane & 7;            // delay-octet sub-lane
    const int oct = lane >> 3;
    const int rp  = 4 * w + oct;         // row-pair owned by this octet
    const float* qq = s_qq + rp * SQ;
    const float* kk = s_kk + rp * SK;
    const int cb0 = 4 * s;               // chunk of element d0 = 8s

    unsigned long long W[12], acc[8];
    #pragma unroll
    for (int u = 0; u < 4; ++u) {
        ulonglong2 tv = *(const ulonglong2*)(qq + 4 * sw(cb0 + u));
        W[2*u] = tv.x; W[2*u + 1] = tv.y;
    }
    #pragma unroll
    for (int j = 0; j < 8; ++j) acc[j] = 0ull;

    #pragma unroll
    for (int blk = 0; blk < 16; ++blk) {
        ulonglong2 t0 = *(const ulonglong2*)(qq + 4 * sw(cb0 + 2*blk + 4));
        ulonglong2 t1 = *(const ulonglong2*)(qq + 4 * sw(cb0 + 2*blk + 5));
        W[8] = t0.x; W[9] = t0.y; W[10] = t1.x; W[11] = t1.y;
        ulonglong2 ka_ = *(const ulonglong2*)(kk + 4 * sw(2*blk));      // consts: folded
        ulonglong2 kb_ = *(const ulonglong2*)(kk + 4 * sw(2*blk + 1));
        unsigned long long kp[4] = {ka_.x, ka_.y, kb_.x, kb_.y};
        #pragma unroll
        for (int tt = 0; tt < 4; ++tt)
            #pragma unroll
            for (int j = 0; j < 8; ++j)
                ffma2(acc[j], W[tt + j], kp[tt]);
        #pragma unroll
        for (int m = 0; m < 8; ++m) W[m] = W[m + 4];
    }
    __syncwarp();   // all q reads done before aliased corr staging

    // ---------------- split accumulators; stage corr into aliased q region ---
    float ex[8], od[8];
    #pragma unroll
    for (int j = 0; j < 8; ++j) {
        float2 f = *reinterpret_cast<float2*>(&acc[j]);
        ex[j] = f.x; od[j] = f.y;
    }
    {
        float* ce = s_qq + rp * SQ;      // corr row 2rp   : words 0..63
        float* co = ce + 130;            // corr row 2rp+1 : words 130..193 (8B aligned)
        *(float4*)(ce + 8*s)     = make_float4(ex[0], ex[1], ex[2], ex[3]);
        *(float4*)(ce + 8*s + 4) = make_float4(ex[4], ex[5], ex[6], ex[7]);
        *(float2*)(co + 8*s)     = make_float2(od[0], od[1]);
        *(float2*)(co + 8*s + 2) = make_float2(od[2], od[3]);
        *(float2*)(co + 8*s + 4) = make_float2(od[4], od[5]);
        *(float2*)(co + 8*s + 6) = make_float2(od[6], od[7]);
    }

    // ---------------- top-4 + softmax + gather (register candidates) ---------
    #pragma unroll
    for (int pass = 0; pass < 2; ++pass) {
        const int rowl = 8 * w + 2 * oct + pass;
        float av[8];
        #pragma unroll
        for (int j = 0; j < 8; ++j) av[j] = pass ? od[j] : ex[j];

        float wv[4]; int wd[4];
        #pragma unroll
        for (int i = 0; i < 4; ++i) {
            // local argmax over 8 regs, lowest index wins ties
            float bv = av[0]; int bj = 0;
            #pragma unroll
            for (int j = 1; j < 8; ++j)
                if (av[j] > bv) { bv = av[j]; bj = j; }
            int bi = 8 * s + bj;
            // 8-lane butterfly within octet, lexicographic (val desc, idx asc)
            #pragma unroll
            for (int off = 4; off; off >>= 1) {
                float ov = __shfl_xor_sync(0xffffffffu, bv, off);
                int   oi = __shfl_xor_sync(0xffffffffu, bi, off);
                if (ov > bv || (ov == bv && oi < bi)) { bv = ov; bi = oi; }
            }
            wv[i] = bv; wd[i] = bi;
            if (i < 3 && (bi >> 3) == s) {        // owner removes selected slot
                const int jb = bi & 7;
                #pragma unroll
                for (int j = 0; j < 8; ++j)
                    if (j == jb) av[j] = -CUDART_INF_F;
            }
        }

        float p[4]; float z = 0.f;
        #pragma unroll
        for (int i = 0; i < 4; ++i) { p[i] = __expf(wv[i] - wv[0]); z += p[i]; }
        const float rz = 1.f / z;

        // gather from duplicated v: index s + 8m + d <= 126 < 128
        const float* vrow = s_v + rowl * SV;
        float om[8] = {0.f,0.f,0.f,0.f,0.f,0.f,0.f,0.f};
        #pragma unroll
        for (int i = 0; i < 4; ++i) {
            const float pi = p[i] * rz;
            const int base = s + wd[i];
            #pragma unroll
            for (int m = 0; m < 8; ++m)
                om[m] = fmaf(pi, vrow[base + 8*m], om[m]);
        }
        const size_t vb = ((size_t)bh * L_ + l0 + rowl) * (size_t)E_;
        #pragma unroll
        for (int m = 0; m < 8; ++m)
            outV[vb + s + 8*m] = om[m];
    }

    // ---------------- transposed corr write: outC[b,e,h,l] -------------------
    __syncthreads();
    #pragma unroll
    for (int idx = t; idx < E_ * ROWS; idx += NTHREADS) {
        int e = idx >> 5;            // ROWS == 32
        int r = idx & 31;
        float val = s_qq[(r >> 1) * SQ + (r & 1) * 130 + e];
        outC[(((size_t)b * E_ + e) * H_ + h) * (size_t)L_ + l0 + r] = val;
    }
}

extern "C" void kernel_launch(void* const* d_in, const int* in_sizes, int n_in,
                              void* d_out, int out_size)
{
    const float* Q = (const float*)d_in[0];
    const float* K = (const float*)d_in[1];
    const float* V = (const float*)d_in[2];
    float* outV = (float*)d_out;
    float* outC = outV + (size_t)B_ * H_ * L_ * E_;

    dim3 grid(L_ / ROWS, B_ * H_);
    ac_kernel<<<grid, NTHREADS>>>(Q, K, V, outV, outC);
}